// round 9
// baseline (speedup 1.0000x reference)
#include <cuda_runtime.h>
#include <cuda_fp16.h>
#include <math.h>

// ---------------------------------------------------------------------------
// AGNN — fp16 normalized features; fused edge kernel with 4 lanes/edge,
// 8 edges/warp, uint4 gathers (one LDG.128 per row), 2-shuffle dots.
//   hn[node] = h/||h|| fp16 (64 B/row), norm[node] = max(||h||,eps).
//   edge: v = exp(beta * dot(hn_s,hn_d)); denom[d] += v;
//         agg[d] += (v*norm[s]) * hn[s]   (f32 vec4 RED)
//   node: h' = relu(agg/denom) -> renorm (mid) / fused into head (last).
// Max-subtraction skipped: |e| <= |beta| (cosine bounded) — same math.
// ---------------------------------------------------------------------------

#define NN 100000
#define NE 1600000
#define EPSF 1e-12f

__device__ __align__(128) float  g_agg[NN * 32];
__device__ __align__(128) __half g_hnA[NN * 32];
__device__ __align__(128) __half g_hnB[NN * 32];
__device__ __align__(128) float  g_norm[NN];
__device__ __align__(128) float  g_denom[NN];

// ---------------------------------------------------------------------------
__global__ void k_zero_layer(float4* __restrict__ agg, float4* __restrict__ denom,
                             int n_agg4, int n_den4) {
    int i = blockIdx.x * blockDim.x + threadIdx.x;
    if (i < n_agg4) agg[i] = make_float4(0.f, 0.f, 0.f, 0.f);
    if (i < n_den4) denom[i] = make_float4(0.f, 0.f, 0.f, 0.f);
}

// ---------------------------------------------------------------------------
// GEMM1: h1 = relu(F @ w1^T + b1); write hn fp16 + norm.
__global__ __launch_bounds__(256) void k_gemm1(
    const float* __restrict__ feat, const float* __restrict__ w1,
    const float* __restrict__ b1, __half* __restrict__ hn,
    float* __restrict__ normv, int n)
{
    __shared__ float w1t[128 * 32];
    __shared__ float b1s[32];
    for (int i = threadIdx.x; i < 4096; i += 256) {
        int j = i >> 7, k = i & 127;
        w1t[k * 32 + j] = w1[i];
    }
    if (threadIdx.x < 32) b1s[threadIdx.x] = b1[threadIdx.x];
    __syncthreads();

    int node = blockIdx.x * 256 + threadIdx.x;
    if (node >= n) return;

    float acc[32];
    #pragma unroll
    for (int j = 0; j < 32; j++) acc[j] = b1s[j];

    const float4* f4 = reinterpret_cast<const float4*>(feat + (size_t)node * 128);
    #pragma unroll 4
    for (int k4 = 0; k4 < 32; k4++) {
        float4 f = f4[k4];
        float fv[4] = {f.x, f.y, f.z, f.w};
        #pragma unroll
        for (int c = 0; c < 4; c++) {
            const float4* w4 = reinterpret_cast<const float4*>(&w1t[(k4 * 4 + c) * 32]);
            #pragma unroll
            for (int j4 = 0; j4 < 8; j4++) {
                float4 w = w4[j4];
                acc[j4 * 4 + 0] += fv[c] * w.x;
                acc[j4 * 4 + 1] += fv[c] * w.y;
                acc[j4 * 4 + 2] += fv[c] * w.z;
                acc[j4 * 4 + 3] += fv[c] * w.w;
            }
        }
    }

    float ss = 0.f;
    #pragma unroll
    for (int j = 0; j < 32; j++) {
        float v = fmaxf(acc[j], 0.f);
        acc[j] = v;
        ss += v * v;
    }
    float nv = fmaxf(sqrtf(ss), EPSF);
    float rinv = 1.0f / nv;
    normv[node] = nv;

    __half2 hp[16];
    #pragma unroll
    for (int j = 0; j < 16; j++)
        hp[j] = __floats2half2_rn(acc[2 * j] * rinv, acc[2 * j + 1] * rinv);
    uint4* o = reinterpret_cast<uint4*>(hn + (size_t)node * 32);
    const uint4* s4 = reinterpret_cast<const uint4*>(hp);
    #pragma unroll
    for (int j = 0; j < 4; j++) o[j] = s4[j];
}

// ---------------------------------------------------------------------------
// Fused edge pass: 4 lanes/edge, 8 edges/warp, uint4 gathers.
__global__ __launch_bounds__(256) void k_edge_fused(
    const int* __restrict__ src, const int* __restrict__ dst,
    const __half* __restrict__ hn, const float* __restrict__ normv,
    const float* __restrict__ betas, int layer,
    float* __restrict__ denom, float* __restrict__ agg, int ne)
{
    int gid  = blockIdx.x * 256 + threadIdx.x;
    int e    = gid >> 2;           // 4 lanes per edge
    int l4   = threadIdx.x & 3;    // 16-B chunk id (0..3) within 64-B row
    if (e >= ne) return;
    unsigned mask = __activemask();

    int s = src[e];
    int d = dst[e];

    // one LDG.128 per row per 4-lane group (16 B/lane = 8 halves)
    uint4 pa = *(reinterpret_cast<const uint4*>(hn + (size_t)s * 32) + l4);
    uint4 pb = *(reinterpret_cast<const uint4*>(hn + (size_t)d * 32) + l4);

    float2 a0 = __half22float2(*reinterpret_cast<const __half2*>(&pa.x));
    float2 a1 = __half22float2(*reinterpret_cast<const __half2*>(&pa.y));
    float2 a2 = __half22float2(*reinterpret_cast<const __half2*>(&pa.z));
    float2 a3 = __half22float2(*reinterpret_cast<const __half2*>(&pa.w));
    float2 b0 = __half22float2(*reinterpret_cast<const __half2*>(&pb.x));
    float2 b1 = __half22float2(*reinterpret_cast<const __half2*>(&pb.y));
    float2 b2 = __half22float2(*reinterpret_cast<const __half2*>(&pb.z));
    float2 b3 = __half22float2(*reinterpret_cast<const __half2*>(&pb.w));

    float p = a0.x * b0.x + a0.y * b0.y + a1.x * b1.x + a1.y * b1.y
            + a2.x * b2.x + a2.y * b2.y + a3.x * b3.x + a3.y * b3.y;
    p += __shfl_xor_sync(mask, p, 1);
    p += __shfl_xor_sync(mask, p, 2);   // full 32-elem dot in all 4 lanes

    float v = __expf(__ldg(&betas[layer]) * p);
    float w = v * __ldg(&normv[s]);

    if (l4 == 0) atomicAdd(&denom[d], v);
    float4* o = reinterpret_cast<float4*>(agg + (size_t)d * 32) + l4 * 2;
    atomicAdd(o,     make_float4(w * a0.x, w * a0.y, w * a1.x, w * a1.y));
    atomicAdd(o + 1, make_float4(w * a2.x, w * a2.y, w * a3.x, w * a3.y));
}

// ---------------------------------------------------------------------------
// Layer-0 node pass, 8 lanes/node: h = relu(agg/denom); write hn fp16 + norm.
__global__ __launch_bounds__(256) void k_norm_mid(
    const float* __restrict__ agg, const float* __restrict__ denom,
    __half* __restrict__ hn, float* __restrict__ normv, int n)
{
    int gid  = blockIdx.x * 256 + threadIdx.x;
    int node = gid >> 3;
    int lane = threadIdx.x & 7;
    if (node >= n) return;
    unsigned mask = __activemask();

    float inv = 1.0f / fmaxf(denom[node], EPSF);
    float4 v = *(reinterpret_cast<const float4*>(agg + (size_t)node * 32) + lane);
    v.x = fmaxf(v.x * inv, 0.f); v.y = fmaxf(v.y * inv, 0.f);
    v.z = fmaxf(v.z * inv, 0.f); v.w = fmaxf(v.w * inv, 0.f);

    float ss = v.x * v.x + v.y * v.y + v.z * v.z + v.w * v.w;
    ss += __shfl_xor_sync(mask, ss, 1);
    ss += __shfl_xor_sync(mask, ss, 2);
    ss += __shfl_xor_sync(mask, ss, 4);

    float nv = fmaxf(sqrtf(ss), EPSF);
    float rinv = 1.0f / nv;
    if (lane == 0) normv[node] = nv;

    __half2 h0 = __floats2half2_rn(v.x * rinv, v.y * rinv);
    __half2 h1 = __floats2half2_rn(v.z * rinv, v.w * rinv);
    uint2 pk;
    pk.x = *reinterpret_cast<unsigned*>(&h0);
    pk.y = *reinterpret_cast<unsigned*>(&h1);
    *(reinterpret_cast<uint2*>(hn + (size_t)node * 32) + lane) = pk;
}

// ---------------------------------------------------------------------------
// Head: h2 = relu(agg/denom); out = log_softmax(h2 @ w2^T + b2).
__global__ __launch_bounds__(128) void k_final(
    const float* __restrict__ agg, const float* __restrict__ denom,
    const float* __restrict__ w2, const float* __restrict__ b2,
    float* __restrict__ out, int n)
{
    __shared__ float w2t[32 * 64];
    __shared__ float b2s[64];
    for (int i = threadIdx.x; i < 2048; i += 128) {
        int j = i >> 5, k = i & 31;
        w2t[k * 64 + j] = w2[i];
    }
    for (int i = threadIdx.x; i < 64; i += 128) b2s[i] = b2[i];
    __syncthreads();

    int node = blockIdx.x * 128 + threadIdx.x;
    if (node >= n) return;

    float inv = 1.0f / fmaxf(denom[node], EPSF);

    float acc[64];
    #pragma unroll
    for (int j = 0; j < 64; j++) acc[j] = b2s[j];

    const float4* h4 = reinterpret_cast<const float4*>(agg + (size_t)node * 32);
    #pragma unroll
    for (int k4 = 0; k4 < 8; k4++) {
        float4 hv = h4[k4];
        float hh[4] = {fmaxf(hv.x * inv, 0.f), fmaxf(hv.y * inv, 0.f),
                       fmaxf(hv.z * inv, 0.f), fmaxf(hv.w * inv, 0.f)};
        #pragma unroll
        for (int c = 0; c < 4; c++) {
            const float4* w4 = reinterpret_cast<const float4*>(&w2t[(k4 * 4 + c) * 64]);
            float f = hh[c];
            #pragma unroll
            for (int j4 = 0; j4 < 16; j4++) {
                float4 w = w4[j4];
                acc[j4 * 4 + 0] += f * w.x;
                acc[j4 * 4 + 1] += f * w.y;
                acc[j4 * 4 + 2] += f * w.z;
                acc[j4 * 4 + 3] += f * w.w;
            }
        }
    }

    float mx = acc[0];
    #pragma unroll
    for (int j = 1; j < 64; j++) mx = fmaxf(mx, acc[j]);
    float sum = 0.f;
    #pragma unroll
    for (int j = 0; j < 64; j++) sum += __expf(acc[j] - mx);
    float lse = mx + __logf(sum);

    float4* o4 = reinterpret_cast<float4*>(out + (size_t)node * 64);
    #pragma unroll
    for (int j4 = 0; j4 < 16; j4++)
        o4[j4] = make_float4(acc[j4 * 4] - lse, acc[j4 * 4 + 1] - lse,
                             acc[j4 * 4 + 2] - lse, acc[j4 * 4 + 3] - lse);
}

// ---------------------------------------------------------------------------
extern "C" void kernel_launch(void* const* d_in, const int* in_sizes, int n_in,
                              void* d_out, int out_size)
{
    const float* feat  = (const float*)d_in[0];
    const int*   src   = (const int*)d_in[1];
    const int*   dst   = (const int*)d_in[2];
    const float* w1    = (const float*)d_in[3];
    const float* b1    = (const float*)d_in[4];
    const float* betas = (const float*)d_in[5];
    const float* w2    = (const float*)d_in[6];
    const float* b2    = (const float*)d_in[7];
    float*       out   = (float*)d_out;

    const int n  = in_sizes[0] / 128;   // 100000
    const int ne = in_sizes[1];         // 1600000

    float *agg, *normv, *denom;
    __half *hnA, *hnB;
    cudaGetSymbolAddress((void**)&agg,   g_agg);
    cudaGetSymbolAddress((void**)&hnA,   g_hnA);
    cudaGetSymbolAddress((void**)&hnB,   g_hnB);
    cudaGetSymbolAddress((void**)&normv, g_norm);
    cudaGetSymbolAddress((void**)&denom, g_denom);

    const int TB = 256;
    const int n_agg4 = n * 32 / 4;
    const int n_den4 = n / 4;
    dim3 gN((n + TB - 1) / TB);
    dim3 gN8(((size_t)n * 8 + TB - 1) / TB);
    dim3 gE4(((size_t)ne * 4 + TB - 1) / TB);
    dim3 gZ((n_agg4 + TB - 1) / TB);

    // K1: hn0/norm0
    k_gemm1<<<gN, TB>>>(feat, w1, b1, hnA, normv, n);

    // ---- layer 0 ----
    k_zero_layer<<<gZ, TB>>>((float4*)agg, (float4*)denom, n_agg4, n_den4);
    k_edge_fused<<<gE4, TB>>>(src, dst, hnA, normv, betas, 0, denom, agg, ne);
    k_norm_mid<<<gN8, TB>>>(agg, denom, hnB, normv, n);

    // ---- layer 1 ----
    k_zero_layer<<<gZ, TB>>>((float4*)agg, (float4*)denom, n_agg4, n_den4);
    k_edge_fused<<<gE4, TB>>>(src, dst, hnB, normv, betas, 1, denom, agg, ne);

    // Head (divide + relu fused)
    k_final<<<(n + 127) / 128, 128>>>(agg, denom, w2, b2, out, n);
}

// round 10
// speedup vs baseline: 1.1599x; 1.1599x over previous
#include <cuda_runtime.h>
#include <cuda_fp16.h>
#include <math.h>

// ---------------------------------------------------------------------------
// AGNN — fp16 normalized features; fused edge kernel: 8 lanes/edge,
// 4 edges per lane-group (16 gather chains/warp), f32 vec4 RED scatter.
//   hn[node] = h/||h|| fp16 (64 B/row), norm[node] = max(||h||,eps).
//   edge: v = exp(beta * dot(hn_s,hn_d)); denom[d] += v;
//         agg[d] += (v*norm[s]) * hn[s]
//   node: h' = relu(agg/denom) -> renorm (mid) / fused into head (last).
// Max-subtraction skipped: |e| <= |beta| (cosine bounded) — same math.
// Double-buffered agg/denom, zeroed once upfront.
// ---------------------------------------------------------------------------

#define NN 100000
#define NE 1600000
#define EPSF 1e-12f

__device__ __align__(128) float  g_aggA[NN * 32];
__device__ __align__(128) float  g_aggB[NN * 32];
__device__ __align__(128) __half g_hnA[NN * 32];
__device__ __align__(128) __half g_hnB[NN * 32];
__device__ __align__(128) float  g_norm[NN];
__device__ __align__(128) float  g_denomA[NN];
__device__ __align__(128) float  g_denomB[NN];

// ---------------------------------------------------------------------------
// Zero both agg buffers and both denom buffers in one kernel.
__global__ void k_zero_all(float4* __restrict__ aggA, float4* __restrict__ aggB,
                           float4* __restrict__ denA, float4* __restrict__ denB,
                           int n_agg4, int n_den4) {
    int i = blockIdx.x * blockDim.x + threadIdx.x;
    float4 z = make_float4(0.f, 0.f, 0.f, 0.f);
    if (i < n_agg4) { aggA[i] = z; aggB[i] = z; }
    if (i < n_den4) { denA[i] = z; denB[i] = z; }
}

// ---------------------------------------------------------------------------
// GEMM1: h1 = relu(F @ w1^T + b1); write hn fp16 + norm.
__global__ __launch_bounds__(256) void k_gemm1(
    const float* __restrict__ feat, const float* __restrict__ w1,
    const float* __restrict__ b1, __half* __restrict__ hn,
    float* __restrict__ normv, int n)
{
    __shared__ float w1t[128 * 32];
    __shared__ float b1s[32];
    for (int i = threadIdx.x; i < 4096; i += 256) {
        int j = i >> 7, k = i & 127;
        w1t[k * 32 + j] = w1[i];
    }
    if (threadIdx.x < 32) b1s[threadIdx.x] = b1[threadIdx.x];
    __syncthreads();

    int node = blockIdx.x * 256 + threadIdx.x;
    if (node >= n) return;

    float acc[32];
    #pragma unroll
    for (int j = 0; j < 32; j++) acc[j] = b1s[j];

    const float4* f4 = reinterpret_cast<const float4*>(feat + (size_t)node * 128);
    #pragma unroll 4
    for (int k4 = 0; k4 < 32; k4++) {
        float4 f = f4[k4];
        float fv[4] = {f.x, f.y, f.z, f.w};
        #pragma unroll
        for (int c = 0; c < 4; c++) {
            const float4* w4 = reinterpret_cast<const float4*>(&w1t[(k4 * 4 + c) * 32]);
            #pragma unroll
            for (int j4 = 0; j4 < 8; j4++) {
                float4 w = w4[j4];
                acc[j4 * 4 + 0] += fv[c] * w.x;
                acc[j4 * 4 + 1] += fv[c] * w.y;
                acc[j4 * 4 + 2] += fv[c] * w.z;
                acc[j4 * 4 + 3] += fv[c] * w.w;
            }
        }
    }

    float ss = 0.f;
    #pragma unroll
    for (int j = 0; j < 32; j++) {
        float v = fmaxf(acc[j], 0.f);
        acc[j] = v;
        ss += v * v;
    }
    float nv = fmaxf(sqrtf(ss), EPSF);
    float rinv = 1.0f / nv;
    normv[node] = nv;

    __half2 hp[16];
    #pragma unroll
    for (int j = 0; j < 16; j++)
        hp[j] = __floats2half2_rn(acc[2 * j] * rinv, acc[2 * j + 1] * rinv);
    uint4* o = reinterpret_cast<uint4*>(hn + (size_t)node * 32);
    const uint4* s4 = reinterpret_cast<const uint4*>(hp);
    #pragma unroll
    for (int j = 0; j < 4; j++) o[j] = s4[j];
}

// ---------------------------------------------------------------------------
// Fused edge pass: 8 lanes/edge, 4 edges per lane-group.
__global__ __launch_bounds__(256) void k_edge_fused(
    const int* __restrict__ src, const int* __restrict__ dst,
    const __half* __restrict__ hn, const float* __restrict__ normv,
    const float* __restrict__ betas, int layer,
    float* __restrict__ denom, float* __restrict__ agg, int ne)
{
    int gid   = blockIdx.x * 256 + threadIdx.x;
    int group = gid >> 3;
    int lane  = threadIdx.x & 7;
    int ebase = group * 4;
    if (ebase >= ne) return;
    unsigned mask = __activemask();

    int s[4], d[4];
    #pragma unroll
    for (int k = 0; k < 4; k++) {
        int e = ebase + k;
        bool ok = (e < ne);
        s[k] = ok ? src[e] : src[ebase];
        d[k] = ok ? dst[e] : dst[ebase];
    }

    // 8 independent gathers per thread in flight
    uint2 pa[4], pb[4];
    #pragma unroll
    for (int k = 0; k < 4; k++) {
        pa[k] = *(reinterpret_cast<const uint2*>(hn + (size_t)s[k] * 32) + lane);
        pb[k] = *(reinterpret_cast<const uint2*>(hn + (size_t)d[k] * 32) + lane);
    }

    float beta = __ldg(&betas[layer]);
    float2 a0[4], a1[4];
    float p[4];
    #pragma unroll
    for (int k = 0; k < 4; k++) {
        a0[k] = __half22float2(*reinterpret_cast<const __half2*>(&pa[k].x));
        a1[k] = __half22float2(*reinterpret_cast<const __half2*>(&pa[k].y));
        float2 b0 = __half22float2(*reinterpret_cast<const __half2*>(&pb[k].x));
        float2 b1 = __half22float2(*reinterpret_cast<const __half2*>(&pb[k].y));
        p[k] = a0[k].x * b0.x + a0[k].y * b0.y + a1[k].x * b1.x + a1[k].y * b1.y;
    }
    #pragma unroll
    for (int k = 0; k < 4; k++) p[k] += __shfl_xor_sync(mask, p[k], 1);
    #pragma unroll
    for (int k = 0; k < 4; k++) p[k] += __shfl_xor_sync(mask, p[k], 2);
    #pragma unroll
    for (int k = 0; k < 4; k++) p[k] += __shfl_xor_sync(mask, p[k], 4);

    #pragma unroll
    for (int k = 0; k < 4; k++) {
        if (ebase + k >= ne) break;
        float v = __expf(beta * p[k]);
        float w = v * __ldg(&normv[s[k]]);
        if (lane == 0) atomicAdd(&denom[d[k]], v);
        atomicAdd(reinterpret_cast<float4*>(agg + (size_t)d[k] * 32) + lane,
                  make_float4(w * a0[k].x, w * a0[k].y, w * a1[k].x, w * a1[k].y));
    }
}

// ---------------------------------------------------------------------------
// Layer-0 node pass, 8 lanes/node: h = relu(agg/denom); write hn fp16 + norm.
__global__ __launch_bounds__(256) void k_norm_mid(
    const float* __restrict__ agg, const float* __restrict__ denom,
    __half* __restrict__ hn, float* __restrict__ normv, int n)
{
    int gid  = blockIdx.x * 256 + threadIdx.x;
    int node = gid >> 3;
    int lane = threadIdx.x & 7;
    if (node >= n) return;
    unsigned mask = __activemask();

    float inv = 1.0f / fmaxf(denom[node], EPSF);
    float4 v = *(reinterpret_cast<const float4*>(agg + (size_t)node * 32) + lane);
    v.x = fmaxf(v.x * inv, 0.f); v.y = fmaxf(v.y * inv, 0.f);
    v.z = fmaxf(v.z * inv, 0.f); v.w = fmaxf(v.w * inv, 0.f);

    float ss = v.x * v.x + v.y * v.y + v.z * v.z + v.w * v.w;
    ss += __shfl_xor_sync(mask, ss, 1);
    ss += __shfl_xor_sync(mask, ss, 2);
    ss += __shfl_xor_sync(mask, ss, 4);

    float nv = fmaxf(sqrtf(ss), EPSF);
    float rinv = 1.0f / nv;
    if (lane == 0) normv[node] = nv;

    __half2 h0 = __floats2half2_rn(v.x * rinv, v.y * rinv);
    __half2 h1 = __floats2half2_rn(v.z * rinv, v.w * rinv);
    uint2 pk;
    pk.x = *reinterpret_cast<unsigned*>(&h0);
    pk.y = *reinterpret_cast<unsigned*>(&h1);
    *(reinterpret_cast<uint2*>(hn + (size_t)node * 32) + lane) = pk;
}

// ---------------------------------------------------------------------------
// Head: h2 = relu(agg/denom); out = log_softmax(h2 @ w2^T + b2).
__global__ __launch_bounds__(128) void k_final(
    const float* __restrict__ agg, const float* __restrict__ denom,
    const float* __restrict__ w2, const float* __restrict__ b2,
    float* __restrict__ out, int n)
{
    __shared__ float w2t[32 * 64];
    __shared__ float b2s[64];
    for (int i = threadIdx.x; i < 2048; i += 128) {
        int j = i >> 5, k = i & 31;
        w2t[k * 64 + j] = w2[i];
    }
    for (int i = threadIdx.x; i < 64; i += 128) b2s[i] = b2[i];
    __syncthreads();

    int node = blockIdx.x * 128 + threadIdx.x;
    if (node >= n) return;

    float inv = 1.0f / fmaxf(denom[node], EPSF);

    float acc[64];
    #pragma unroll
    for (int j = 0; j < 64; j++) acc[j] = b2s[j];

    const float4* h4 = reinterpret_cast<const float4*>(agg + (size_t)node * 32);
    #pragma unroll
    for (int k4 = 0; k4 < 8; k4++) {
        float4 hv = h4[k4];
        float hh[4] = {fmaxf(hv.x * inv, 0.f), fmaxf(hv.y * inv, 0.f),
                       fmaxf(hv.z * inv, 0.f), fmaxf(hv.w * inv, 0.f)};
        #pragma unroll
        for (int c = 0; c < 4; c++) {
            const float4* w4 = reinterpret_cast<const float4*>(&w2t[(k4 * 4 + c) * 64]);
            float f = hh[c];
            #pragma unroll
            for (int j4 = 0; j4 < 16; j4++) {
                float4 w = w4[j4];
                acc[j4 * 4 + 0] += f * w.x;
                acc[j4 * 4 + 1] += f * w.y;
                acc[j4 * 4 + 2] += f * w.z;
                acc[j4 * 4 + 3] += f * w.w;
            }
        }
    }

    float mx = acc[0];
    #pragma unroll
    for (int j = 1; j < 64; j++) mx = fmaxf(mx, acc[j]);
    float sum = 0.f;
    #pragma unroll
    for (int j = 0; j < 64; j++) sum += __expf(acc[j] - mx);
    float lse = mx + __logf(sum);

    float4* o4 = reinterpret_cast<float4*>(out + (size_t)node * 64);
    #pragma unroll
    for (int j4 = 0; j4 < 16; j4++)
        o4[j4] = make_float4(acc[j4 * 4] - lse, acc[j4 * 4 + 1] - lse,
                             acc[j4 * 4 + 2] - lse, acc[j4 * 4 + 3] - lse);
}

// ---------------------------------------------------------------------------
extern "C" void kernel_launch(void* const* d_in, const int* in_sizes, int n_in,
                              void* d_out, int out_size)
{
    const float* feat  = (const float*)d_in[0];
    const int*   src   = (const int*)d_in[1];
    const int*   dst   = (const int*)d_in[2];
    const float* w1    = (const float*)d_in[3];
    const float* b1    = (const float*)d_in[4];
    const float* betas = (const float*)d_in[5];
    const float* w2    = (const float*)d_in[6];
    const float* b2    = (const float*)d_in[7];
    float*       out   = (float*)d_out;

    const int n  = in_sizes[0] / 128;   // 100000
    const int ne = in_sizes[1];         // 1600000

    float *aggA, *aggB, *normv, *denA, *denB;
    __half *hnA, *hnB;
    cudaGetSymbolAddress((void**)&aggA,  g_aggA);
    cudaGetSymbolAddress((void**)&aggB,  g_aggB);
    cudaGetSymbolAddress((void**)&hnA,   g_hnA);
    cudaGetSymbolAddress((void**)&hnB,   g_hnB);
    cudaGetSymbolAddress((void**)&normv, g_norm);
    cudaGetSymbolAddress((void**)&denA,  g_denomA);
    cudaGetSymbolAddress((void**)&denB,  g_denomB);

    const int TB = 256;
    const int n_agg4 = n * 32 / 4;
    const int n_den4 = n / 4;
    const int ngroups = (ne + 3) / 4;
    dim3 gN((n + TB - 1) / TB);
    dim3 gN8(((size_t)n * 8 + TB - 1) / TB);
    dim3 gG8(((size_t)ngroups * 8 + TB - 1) / TB);
    dim3 gZ((n_agg4 + TB - 1) / TB);

    // Zero all accumulators once upfront (A and B buffers).
    k_zero_all<<<gZ, TB>>>((float4*)aggA, (float4*)aggB,
                           (float4*)denA, (float4*)denB, n_agg4, n_den4);

    // K1: hn0/norm0
    k_gemm1<<<gN, TB>>>(feat, w1, b1, hnA, normv, n);

    // ---- layer 0: hnA -> aggA/denA -> hnB ----
    k_edge_fused<<<gG8, TB>>>(src, dst, hnA, normv, betas, 0, denA, aggA, ne);
    k_norm_mid<<<gN8, TB>>>(aggA, denA, hnB, normv, n);

    // ---- layer 1: hnB -> aggB/denB ----
    k_edge_fused<<<gG8, TB>>>(src, dst, hnB, normv, betas, 1, denB, aggB, ne);

    // Head (divide + relu fused)
    k_final<<<(n + 127) / 128, 128>>>(aggB, denB, w2, b2, out, n);
}

// round 11
// speedup vs baseline: 1.1705x; 1.0091x over previous
#include <cuda_runtime.h>
#include <cuda_fp16.h>
#include <math.h>

// ---------------------------------------------------------------------------
// AGNN — fp16 normalized features; fused edge kernel: 8 lanes/edge,
// 4 edges per lane-group, HFMA2 packed dot (fewer issue slots), f32 RED.
//   hn[node] = h/||h|| fp16 (64 B/row), norm[node] = max(||h||,eps).
//   edge: v = exp(beta * dot(hn_s,hn_d)); denom[d] += v;
//         agg[d] += (v*norm[s]) * hn[s]
//   node: h' = relu(agg/denom) -> renorm (mid) / fused into head (last).
// Max-subtraction skipped: |e| <= |beta| (cosine bounded) — same math.
// ---------------------------------------------------------------------------

#define NN 100000
#define NE 1600000
#define EPSF 1e-12f

__device__ __align__(128) float  g_aggA[NN * 32];
__device__ __align__(128) float  g_aggB[NN * 32];
__device__ __align__(128) __half g_hnA[NN * 32];
__device__ __align__(128) __half g_hnB[NN * 32];
__device__ __align__(128) float  g_norm[NN];
__device__ __align__(128) float  g_denomA[NN];
__device__ __align__(128) float  g_denomB[NN];

// ---------------------------------------------------------------------------
__global__ void k_zero_all(float4* __restrict__ aggA, float4* __restrict__ aggB,
                           float4* __restrict__ denA, float4* __restrict__ denB,
                           int n_agg4, int n_den4) {
    int i = blockIdx.x * blockDim.x + threadIdx.x;
    float4 z = make_float4(0.f, 0.f, 0.f, 0.f);
    if (i < n_agg4) { aggA[i] = z; aggB[i] = z; }
    if (i < n_den4) { denA[i] = z; denB[i] = z; }
}

// ---------------------------------------------------------------------------
// GEMM1: h1 = relu(F @ w1^T + b1); write hn fp16 + norm.
__global__ __launch_bounds__(256) void k_gemm1(
    const float* __restrict__ feat, const float* __restrict__ w1,
    const float* __restrict__ b1, __half* __restrict__ hn,
    float* __restrict__ normv, int n)
{
    __shared__ float w1t[128 * 32];
    __shared__ float b1s[32];
    for (int i = threadIdx.x; i < 4096; i += 256) {
        int j = i >> 7, k = i & 127;
        w1t[k * 32 + j] = w1[i];
    }
    if (threadIdx.x < 32) b1s[threadIdx.x] = b1[threadIdx.x];
    __syncthreads();

    int node = blockIdx.x * 256 + threadIdx.x;
    if (node >= n) return;

    float acc[32];
    #pragma unroll
    for (int j = 0; j < 32; j++) acc[j] = b1s[j];

    const float4* f4 = reinterpret_cast<const float4*>(feat + (size_t)node * 128);
    #pragma unroll 4
    for (int k4 = 0; k4 < 32; k4++) {
        float4 f = f4[k4];
        float fv[4] = {f.x, f.y, f.z, f.w};
        #pragma unroll
        for (int c = 0; c < 4; c++) {
            const float4* w4 = reinterpret_cast<const float4*>(&w1t[(k4 * 4 + c) * 32]);
            #pragma unroll
            for (int j4 = 0; j4 < 8; j4++) {
                float4 w = w4[j4];
                acc[j4 * 4 + 0] += fv[c] * w.x;
                acc[j4 * 4 + 1] += fv[c] * w.y;
                acc[j4 * 4 + 2] += fv[c] * w.z;
                acc[j4 * 4 + 3] += fv[c] * w.w;
            }
        }
    }

    float ss = 0.f;
    #pragma unroll
    for (int j = 0; j < 32; j++) {
        float v = fmaxf(acc[j], 0.f);
        acc[j] = v;
        ss += v * v;
    }
    float nv = fmaxf(sqrtf(ss), EPSF);
    float rinv = 1.0f / nv;
    normv[node] = nv;

    __half2 hp[16];
    #pragma unroll
    for (int j = 0; j < 16; j++)
        hp[j] = __floats2half2_rn(acc[2 * j] * rinv, acc[2 * j + 1] * rinv);
    uint4* o = reinterpret_cast<uint4*>(hn + (size_t)node * 32);
    const uint4* s4 = reinterpret_cast<const uint4*>(hp);
    #pragma unroll
    for (int j = 0; j < 4; j++) o[j] = s4[j];
}

// ---------------------------------------------------------------------------
// Fused edge pass: 8 lanes/edge, 4 edges per lane-group, HFMA2 dot.
__global__ __launch_bounds__(256) void k_edge_fused(
    const int* __restrict__ src, const int* __restrict__ dst,
    const __half* __restrict__ hn, const float* __restrict__ normv,
    const float* __restrict__ betas, int layer,
    float* __restrict__ denom, float* __restrict__ agg, int ne)
{
    int gid   = blockIdx.x * 256 + threadIdx.x;
    int group = gid >> 3;
    int lane  = threadIdx.x & 7;
    int ebase = group * 4;
    if (ebase >= ne) return;
    unsigned mask = __activemask();

    int s[4], d[4];
    #pragma unroll
    for (int k = 0; k < 4; k++) {
        int e = ebase + k;
        bool ok = (e < ne);
        s[k] = ok ? src[e] : src[ebase];
        d[k] = ok ? dst[e] : dst[ebase];
    }

    // 8 independent gathers per thread in flight
    uint2 pa[4], pb[4];
    #pragma unroll
    for (int k = 0; k < 4; k++) {
        pa[k] = *(reinterpret_cast<const uint2*>(hn + (size_t)s[k] * 32) + lane);
        pb[k] = *(reinterpret_cast<const uint2*>(hn + (size_t)d[k] * 32) + lane);
    }

    float beta = __ldg(&betas[layer]);
    float p[4];
    #pragma unroll
    for (int k = 0; k < 4; k++) {
        // packed half2 dot: 2 half2 ops + 1 cvt + 1 add per lane-edge
        __half2 A0 = *reinterpret_cast<const __half2*>(&pa[k].x);
        __half2 A1 = *reinterpret_cast<const __half2*>(&pa[k].y);
        __half2 B0 = *reinterpret_cast<const __half2*>(&pb[k].x);
        __half2 B1 = *reinterpret_cast<const __half2*>(&pb[k].y);
        __half2 ph = __hfma2(A0, B0, __hmul2(A1, B1));
        float2 pf = __half22float2(ph);
        p[k] = pf.x + pf.y;
    }
    #pragma unroll
    for (int k = 0; k < 4; k++) p[k] += __shfl_xor_sync(mask, p[k], 1);
    #pragma unroll
    for (int k = 0; k < 4; k++) p[k] += __shfl_xor_sync(mask, p[k], 2);
    #pragma unroll
    for (int k = 0; k < 4; k++) p[k] += __shfl_xor_sync(mask, p[k], 4);

    #pragma unroll
    for (int k = 0; k < 4; k++) {
        if (ebase + k >= ne) break;
        float v = __expf(beta * p[k]);
        float w = v * __ldg(&normv[s[k]]);
        float2 a0 = __half22float2(*reinterpret_cast<const __half2*>(&pa[k].x));
        float2 a1 = __half22float2(*reinterpret_cast<const __half2*>(&pa[k].y));
        if (lane == 0) atomicAdd(&denom[d[k]], v);
        atomicAdd(reinterpret_cast<float4*>(agg + (size_t)d[k] * 32) + lane,
                  make_float4(w * a0.x, w * a0.y, w * a1.x, w * a1.y));
    }
}

// ---------------------------------------------------------------------------
// Layer-0 node pass, 8 lanes/node: h = relu(agg/denom); write hn fp16 + norm.
__global__ __launch_bounds__(256) void k_norm_mid(
    const float* __restrict__ agg, const float* __restrict__ denom,
    __half* __restrict__ hn, float* __restrict__ normv, int n)
{
    int gid  = blockIdx.x * 256 + threadIdx.x;
    int node = gid >> 3;
    int lane = threadIdx.x & 7;
    if (node >= n) return;
    unsigned mask = __activemask();

    float inv = 1.0f / fmaxf(denom[node], EPSF);
    float4 v = *(reinterpret_cast<const float4*>(agg + (size_t)node * 32) + lane);
    v.x = fmaxf(v.x * inv, 0.f); v.y = fmaxf(v.y * inv, 0.f);
    v.z = fmaxf(v.z * inv, 0.f); v.w = fmaxf(v.w * inv, 0.f);

    float ss = v.x * v.x + v.y * v.y + v.z * v.z + v.w * v.w;
    ss += __shfl_xor_sync(mask, ss, 1);
    ss += __shfl_xor_sync(mask, ss, 2);
    ss += __shfl_xor_sync(mask, ss, 4);

    float nv = fmaxf(sqrtf(ss), EPSF);
    float rinv = 1.0f / nv;
    if (lane == 0) normv[node] = nv;

    __half2 h0 = __floats2half2_rn(v.x * rinv, v.y * rinv);
    __half2 h1 = __floats2half2_rn(v.z * rinv, v.w * rinv);
    uint2 pk;
    pk.x = *reinterpret_cast<unsigned*>(&h0);
    pk.y = *reinterpret_cast<unsigned*>(&h1);
    *(reinterpret_cast<uint2*>(hn + (size_t)node * 32) + lane) = pk;
}

// ---------------------------------------------------------------------------
// Head: h2 = relu(agg/denom); out = log_softmax(h2 @ w2^T + b2).
__global__ __launch_bounds__(128) void k_final(
    const float* __restrict__ agg, const float* __restrict__ denom,
    const float* __restrict__ w2, const float* __restrict__ b2,
    float* __restrict__ out, int n)
{
    __shared__ float w2t[32 * 64];
    __shared__ float b2s[64];
    for (int i = threadIdx.x; i < 2048; i += 128) {
        int j = i >> 5, k = i & 31;
        w2t[k * 64 + j] = w2[i];
    }
    for (int i = threadIdx.x; i < 64; i += 128) b2s[i] = b2[i];
    __syncthreads();

    int node = blockIdx.x * 128 + threadIdx.x;
    if (node >= n) return;

    float inv = 1.0f / fmaxf(denom[node], EPSF);

    float acc[64];
    #pragma unroll
    for (int j = 0; j < 64; j++) acc[j] = b2s[j];

    const float4* h4 = reinterpret_cast<const float4*>(agg + (size_t)node * 32);
    #pragma unroll
    for (int k4 = 0; k4 < 8; k4++) {
        float4 hv = h4[k4];
        float hh[4] = {fmaxf(hv.x * inv, 0.f), fmaxf(hv.y * inv, 0.f),
                       fmaxf(hv.z * inv, 0.f), fmaxf(hv.w * inv, 0.f)};
        #pragma unroll
        for (int c = 0; c < 4; c++) {
            const float4* w4 = reinterpret_cast<const float4*>(&w2t[(k4 * 4 + c) * 64]);
            float f = hh[c];
            #pragma unroll
            for (int j4 = 0; j4 < 16; j4++) {
                float4 w = w4[j4];
                acc[j4 * 4 + 0] += f * w.x;
                acc[j4 * 4 + 1] += f * w.y;
                acc[j4 * 4 + 2] += f * w.z;
                acc[j4 * 4 + 3] += f * w.w;
            }
        }
    }

    float mx = acc[0];
    #pragma unroll
    for (int j = 1; j < 64; j++) mx = fmaxf(mx, acc[j]);
    float sum = 0.f;
    #pragma unroll
    for (int j = 0; j < 64; j++) sum += __expf(acc[j] - mx);
    float lse = mx + __logf(sum);

    float4* o4 = reinterpret_cast<float4*>(out + (size_t)node * 64);
    #pragma unroll
    for (int j4 = 0; j4 < 16; j4++)
        o4[j4] = make_float4(acc[j4 * 4] - lse, acc[j4 * 4 + 1] - lse,
                             acc[j4 * 4 + 2] - lse, acc[j4 * 4 + 3] - lse);
}

// ---------------------------------------------------------------------------
extern "C" void kernel_launch(void* const* d_in, const int* in_sizes, int n_in,
                              void* d_out, int out_size)
{
    const float* feat  = (const float*)d_in[0];
    const int*   src   = (const int*)d_in[1];
    const int*   dst   = (const int*)d_in[2];
    const float* w1    = (const float*)d_in[3];
    const float* b1    = (const float*)d_in[4];
    const float* betas = (const float*)d_in[5];
    const float* w2    = (const float*)d_in[6];
    const float* b2    = (const float*)d_in[7];
    float*       out   = (float*)d_out;

    const int n  = in_sizes[0] / 128;   // 100000
    const int ne = in_sizes[1];         // 1600000

    float *aggA, *aggB, *normv, *denA, *denB;
    __half *hnA, *hnB;
    cudaGetSymbolAddress((void**)&aggA,  g_aggA);
    cudaGetSymbolAddress((void**)&aggB,  g_aggB);
    cudaGetSymbolAddress((void**)&hnA,   g_hnA);
    cudaGetSymbolAddress((void**)&hnB,   g_hnB);
    cudaGetSymbolAddress((void**)&normv, g_norm);
    cudaGetSymbolAddress((void**)&denA,  g_denomA);
    cudaGetSymbolAddress((void**)&denB,  g_denomB);

    const int TB = 256;
    const int n_agg4 = n * 32 / 4;
    const int n_den4 = n / 4;
    const int ngroups = (ne + 3) / 4;
    dim3 gN((n + TB - 1) / TB);
    dim3 gN8(((size_t)n * 8 + TB - 1) / TB);
    dim3 gG8(((size_t)ngroups * 8 + TB - 1) / TB);
    dim3 gZ((n_agg4 + TB - 1) / TB);

    // Zero all accumulators once upfront (A and B buffers).
    k_zero_all<<<gZ, TB>>>((float4*)aggA, (float4*)aggB,
                           (float4*)denA, (float4*)denB, n_agg4, n_den4);

    // K1: hn0/norm0
    k_gemm1<<<gN, TB>>>(feat, w1, b1, hnA, normv, n);

    // ---- layer 0: hnA -> aggA/denA -> hnB ----
    k_edge_fused<<<gG8, TB>>>(src, dst, hnA, normv, betas, 0, denA, aggA, ne);
    k_norm_mid<<<gN8, TB>>>(aggA, denA, hnB, normv, n);

    // ---- layer 1: hnB -> aggB/denB ----
    k_edge_fused<<<gG8, TB>>>(src, dst, hnB, normv, betas, 1, denB, aggB, ne);

    // Head (divide + relu fused)
    k_final<<<(n + 127) / 128, 128>>>(aggB, denB, w2, b2, out, n);
}